// round 9
// baseline (speedup 1.0000x reference)
#include <cuda_runtime.h>

#define NS 512       // sequence length N
#define DD 64        // feature dim d
#define NB 64        // batch B
#define GTJ 64       // column tiles (8 wide each)
#define NDIAG 192    // 128 + 64 - 1 = 191, padded even
#define C2_NEG (-0x40000000)
#define SHIFT 90     // prescale: align tile inputs near 2^90 for headroom

// 64 MB scratch: E[b,i,j] = exp(-||x_i - y_j||)
__device__ float g_E[(size_t)NB * NS * NS];

// ---------------------------------------------------------------------------
// Packed f32x2 FMA (Blackwell)
// ---------------------------------------------------------------------------
__device__ __forceinline__ void fma2(unsigned long long& d,
                                     unsigned long long a,
                                     unsigned long long b) {
    asm("fma.rn.f32x2 %0, %1, %2, %0;" : "+l"(d) : "l"(a), "l"(b));
}

// ---------------------------------------------------------------------------
// Stage 1: E[b,i,j] = exp(-sqrt(max(0, |x_i|^2 + |y_j|^2 - 2 x_i.y_j)))
// (unchanged)
// ---------------------------------------------------------------------------
__global__ void __launch_bounds__(256, 2)
cdist_kernel(const float* __restrict__ X, const float* __restrict__ Y) {
    __shared__ float Xs[64 * 64];
    __shared__ float Ys[64 * 64];
    __shared__ float xn[64], yn[64];

    const int b  = blockIdx.z;
    const int i0 = blockIdx.y * 64;
    const int j0 = blockIdx.x * 64;
    const int tid = threadIdx.y * 16 + threadIdx.x;

    const float* Xg = X + ((size_t)b * NS + i0) * DD;
    const float* Yg = Y + ((size_t)b * NS + j0) * DD;

    float4* Xs4 = reinterpret_cast<float4*>(Xs);
    float4* Ys4 = reinterpret_cast<float4*>(Ys);

#pragma unroll
    for (int t = 0; t < 4; ++t) {
        int lin = t * 256 + tid;
        int row = lin >> 4;
        int k4  = lin & 15;
        int sw  = k4 ^ (row & 15);
        Xs4[row * 16 + sw] = *reinterpret_cast<const float4*>(Xg + row * DD + k4 * 4);
        Ys4[row * 16 + sw] = *reinterpret_cast<const float4*>(Yg + row * DD + k4 * 4);
    }
    __syncthreads();

    if (tid < 128) {
        int r = tid & 63;
        const float4* P = (tid < 64) ? reinterpret_cast<const float4*>(Xs)
                                     : reinterpret_cast<const float4*>(Ys);
        float s = 0.0f;
#pragma unroll
        for (int k4 = 0; k4 < 16; ++k4) {
            float4 v = P[r * 16 + (k4 ^ (r & 15))];
            s += v.x * v.x + v.y * v.y + v.z * v.z + v.w * v.w;
        }
        if (tid < 64) xn[r] = s; else yn[r] = s;
    }
    __syncthreads();

    const int tx = threadIdx.x, ty = threadIdx.y;

    unsigned long long acc[4][4];
#pragma unroll
    for (int r = 0; r < 4; ++r)
#pragma unroll
        for (int c = 0; c < 4; ++c) acc[r][c] = 0ull;

    const ulonglong2* Xs2 = reinterpret_cast<const ulonglong2*>(Xs);
    const ulonglong2* Ys2 = reinterpret_cast<const ulonglong2*>(Ys);

#pragma unroll
    for (int k4 = 0; k4 < 16; ++k4) {
        ulonglong2 av[4], bv[4];
#pragma unroll
        for (int r = 0; r < 4; ++r) {
            int i = ty + 16 * r;
            av[r] = Xs2[i * 16 + (k4 ^ (i & 15))];
        }
#pragma unroll
        for (int c = 0; c < 4; ++c) {
            int j = tx + 16 * c;
            bv[c] = Ys2[j * 16 + (k4 ^ (j & 15))];
        }
#pragma unroll
        for (int r = 0; r < 4; ++r)
#pragma unroll
            for (int c = 0; c < 4; ++c) {
                fma2(acc[r][c], av[r].x, bv[c].x);
                fma2(acc[r][c], av[r].y, bv[c].y);
            }
    }

    float* Eout = g_E + (size_t)b * NS * NS;
#pragma unroll
    for (int r = 0; r < 4; ++r) {
        int i = ty + 16 * r;
#pragma unroll
        for (int c = 0; c < 4; ++c) {
            int j = tx + 16 * c;
            float lo = __uint_as_float((unsigned)(acc[r][c] & 0xffffffffull));
            float hi = __uint_as_float((unsigned)(acc[r][c] >> 32));
            float d2 = xn[i] + yn[j] - 2.0f * (lo + hi);
            float dist = sqrtf(fmaxf(d2, 0.0f));
            Eout[(size_t)(i0 + i) * NS + (j0 + j)] =
                exp2f(-1.4426950408889634f * dist);
        }
    }
}

// ---------------------------------------------------------------------------
// Stage 2: weight-domain soft-DTW, binary scaling.
// 32 CTAs x 128 threads; each CTA runs TWO independent batches. Per thread,
// the two batch tile-chains (4x8 each) are fully independent -> ILP 2 on all
// four SMSPs. Branchless (select-based) tile body so ptxas interleaves them.
// ---------------------------------------------------------------------------
__device__ __forceinline__ float exp2i_s(int e) {
    return (e >= -126) ? __int_as_float((e + 127) << 23) : 0.0f;
}
__device__ __forceinline__ int fexp(float m) {
    return ((__float_as_int(m) >> 23) & 0xff) - 127;
}

struct TS {
    float l0, l1, l2, l3;   // left frontier (renormed)
    int leftC2;
    float cornE;
    int cornC2;
};

// One 4x8 tile; reset at tj==0 is select-based (no branch).
__device__ __forceinline__ void tile8(
    int tj, int ti,
    float4 t0, float4 t1, int sTop,
    const float4 (&eb)[8], TS& st,
    float4& o0, float4& o1, int& oC2,
    float& lastRaw, int& lastC2)
{
    const bool rst = (tj == 0);
    float L0 = rst ? 0.0f : st.l0;
    float L1 = rst ? 0.0f : st.l1;
    float L2 = rst ? 0.0f : st.l2;
    float L3 = rst ? 0.0f : st.l3;
    int   LC = rst ? C2_NEG : st.leftC2;
    float CE = rst ? ((ti == 0) ? 1.0f : 0.0f) : st.cornE;
    int   CC = rst ? ((ti == 0) ? 0 : C2_NEG) : st.cornC2;

    int c2 = max(max(sTop, CC), LC);
    const float ft = exp2i_s(sTop - c2 + SHIFT);
    const float fc = exp2i_s(CC   - c2 + SHIFT);
    const float fl = exp2i_s(LC   - c2 + SHIFT);

    float prev[9];
    prev[0] = CE * fc;
    prev[1] = t0.x * ft; prev[2] = t0.y * ft; prev[3] = t0.z * ft; prev[4] = t0.w * ft;
    prev[5] = t1.x * ft; prev[6] = t1.y * ft; prev[7] = t1.z * ft; prev[8] = t1.w * ft;
    float lE0 = L0 * fl, lE1 = L1 * fl, lE2 = L2 * fl, lE3 = L3 * fl;
    const float newCorn = prev[8];

    float right[4];
#pragma unroll
    for (int a = 0; a < 4; ++a) {
        const float4 eA = eb[2 * a], eB = eb[2 * a + 1];
        const float nl = (a == 0) ? lE0 : (a == 1) ? lE1 : (a == 2) ? lE2 : lE3;
        float carry = prev[0];
        prev[0] = nl;
        float s;
        s = (carry + prev[1]) + prev[0]; carry = prev[1]; prev[1] = eA.x * s;
        s = (carry + prev[2]) + prev[1]; carry = prev[2]; prev[2] = eA.y * s;
        s = (carry + prev[3]) + prev[2]; carry = prev[3]; prev[3] = eA.z * s;
        s = (carry + prev[4]) + prev[3]; carry = prev[4]; prev[4] = eA.w * s;
        s = (carry + prev[5]) + prev[4]; carry = prev[5]; prev[5] = eB.x * s;
        s = (carry + prev[6]) + prev[5]; carry = prev[6]; prev[6] = eB.y * s;
        s = (carry + prev[7]) + prev[6]; carry = prev[7]; prev[7] = eB.z * s;
        s = (carry + prev[8]) + prev[7];                  prev[8] = eB.w * s;
        right[a] = prev[8];
    }

    lastRaw = prev[8];
    lastC2  = c2 - SHIFT;

    // Merged renorm of the 12 outputs.
    float m = fmaxf(fmaxf(fmaxf(prev[1], prev[2]), fmaxf(prev[3], prev[4])),
                    fmaxf(fmaxf(prev[5], prev[6]), fmaxf(prev[7], prev[8])));
    m = fmaxf(m, fmaxf(fmaxf(right[0], right[1]), fmaxf(right[2], right[3])));
    int em = fexp(m);
    float rs = __int_as_float((127 - em) << 23);
    int c2n = (m > 0.0f) ? (c2 - SHIFT + em) : C2_NEG;

    o0 = make_float4(prev[1] * rs, prev[2] * rs, prev[3] * rs, prev[4] * rs);
    o1 = make_float4(prev[5] * rs, prev[6] * rs, prev[7] * rs, prev[8] * rs);
    oC2 = c2n;
    st.l0 = right[0] * rs; st.l1 = right[1] * rs;
    st.l2 = right[2] * rs; st.l3 = right[3] * rs;
    st.leftC2 = c2n;

    int ec = fexp(newCorn);
    st.cornE  = newCorn * __int_as_float((127 - ec) << 23);
    st.cornC2 = (newCorn > 0.0f) ? (c2 - SHIFT + ec) : C2_NEG;
}

__device__ __forceinline__ int clampj(int t) {
    return (t < 0) ? 0 : (t > GTJ - 1 ? GTJ - 1 : t);
}

__device__ __forceinline__ void prefetch8(const float* __restrict__ base,
                                          int tjn, float4 (&nb)[8]) {
    int c8 = clampj(tjn) * 8;
#pragma unroll
    for (int a = 0; a < 4; ++a) {
        nb[2 * a]     = *reinterpret_cast<const float4*>(base + a * NS + c8);
        nb[2 * a + 1] = *reinterpret_cast<const float4*>(base + a * NS + c8 + 4);
    }
}

__device__ __forceinline__ void dp_step2(
    int kd, int ti, int b0,
    const float* __restrict__ Erow0, const float* __restrict__ Erow1,
    const float4 (&cb0)[8], float4 (&nb0)[8],
    const float4 (&cb1)[8], float4 (&nb1)[8],
    float4 (*rowE4)[2][2 * GTJ + 2], int (*rowC2)[2][GTJ + 2],
    TS& S0, TS& S1, float* __restrict__ out)
{
    const int tj  = kd - ti;
    const int wb  = kd & 1, rb = wb ^ 1;
    const bool act = (unsigned)tj < (unsigned)GTJ;
    const int tjr = clampj(tj);

    // Top frontiers for both batches (pre-zeroed = i-1 boundary).
    float4 a0 = rowE4[0][rb][2 * tjr];
    float4 a1 = rowE4[0][rb][2 * tjr + 1];
    int    as = rowC2[0][rb][tjr];
    float4 b0v = rowE4[1][rb][2 * tjr];
    float4 b1v = rowE4[1][rb][2 * tjr + 1];
    int    bs = rowC2[1][rb][tjr];

    // Prefetch next tiles for both batches.
    prefetch8(Erow0, tj + 1, nb0);
    prefetch8(Erow1, tj + 1, nb1);

    // Two fully independent 4x8 chains (different batches).
    float4 o00, o01, o10, o11; int c0, c1;
    float lr0, lr1; int lc0, lc1;
    tile8(tj, ti, a0, a1, as, cb0, S0, o00, o01, c0, lr0, lc0);
    tile8(tj, ti, b0v, b1v, bs, cb1, S1, o10, o11, c1, lr1, lc1);

    // Final cell of each DP: tile (127, 63).
    if (tj == GTJ - 1 && ti == 127) {
        out[b0]     = -(log2f(lr0) + (float)lc0) * 0.69314718055994530942f;
        out[b0 + 1] = -(log2f(lr1) + (float)lc1) * 0.69314718055994530942f;
    }

    const int ws = act ? 2 * tj : 2 * GTJ;   // dummy slots when inactive
    const int wc = act ? tj : GTJ;
    rowE4[0][wb][ws]     = o00;
    rowE4[0][wb][ws + 1] = o01;
    rowC2[0][wb][wc]     = c0;
    rowE4[1][wb][ws]     = o10;
    rowE4[1][wb][ws + 1] = o11;
    rowC2[1][wb][wc]     = c1;
    __syncthreads();
}

__global__ void __launch_bounds__(128, 1)
dp_kernel(float* __restrict__ out) {
    const int b0 = blockIdx.x * 2;
    const float* Eb0 = g_E + (size_t)b0 * NS * NS;
    const float* Eb1 = g_E + (size_t)(b0 + 1) * NS * NS;

    __shared__ __align__(16) float4 rowE4[2][2][2 * GTJ + 2];  // [batch][parity][slot]
    __shared__ int rowC2[2][2][GTJ + 2];

    const int ti = threadIdx.x;
    const float* Erow0 = Eb0 + (size_t)(ti * 4) * NS;
    const float* Erow1 = Eb1 + (size_t)(ti * 4) * NS;

    // Pre-zero both parities of both batches (boundary: W=0, scale C2_NEG).
    {
        float4 z = make_float4(0.f, 0.f, 0.f, 0.f);
        float4* re = &rowE4[0][0][0];
        for (int s = ti; s < 2 * 2 * (2 * GTJ + 2); s += 128) re[s] = z;
        int* rc = &rowC2[0][0][0];
        for (int s = ti; s < 2 * 2 * (GTJ + 2); s += 128) rc[s] = C2_NEG;
    }

    float4 bA0[8], bB0[8], bA1[8], bB1[8];
    prefetch8(Erow0, 0, bA0);
    prefetch8(Erow1, 0, bA1);
#pragma unroll
    for (int a = 0; a < 8; ++a) { bB0[a] = bA0[a]; bB1[a] = bA1[a]; }

    TS S0, S1;
    S0.l0 = S0.l1 = S0.l2 = S0.l3 = 0.f;
    S0.leftC2 = C2_NEG; S0.cornE = 0.f; S0.cornC2 = C2_NEG;
    S1 = S0;

    __syncthreads();

    for (int kd = 0; kd < NDIAG; kd += 2) {
        dp_step2(kd,     ti, b0, Erow0, Erow1, bA0, bB0, bA1, bB1,
                 rowE4, rowC2, S0, S1, out);
        dp_step2(kd + 1, ti, b0, Erow0, Erow1, bB0, bA0, bB1, bA1,
                 rowE4, rowC2, S0, S1, out);
    }
}

// ---------------------------------------------------------------------------
extern "C" void kernel_launch(void* const* d_in, const int* in_sizes, int n_in,
                              void* d_out, int out_size) {
    (void)in_sizes; (void)n_in; (void)out_size;
    const float* X = (const float*)d_in[0];
    const float* Y = (const float*)d_in[1];
    float* out = (float*)d_out;

    dim3 g1(NS / 64, NS / 64, NB);   // (8, 8, 64)
    dim3 b1(16, 16);
    cdist_kernel<<<g1, b1>>>(X, Y);

    dp_kernel<<<NB / 2, 128>>>(out);
}